// round 2
// baseline (speedup 1.0000x reference)
#include <cuda_runtime.h>

// Problem constants
#define BB 4
#define NN 2048
#define FF 128
#define HH 256
#define CC 64
#define MAXN 512            // max neighbors per row (mean ~200, sigma ~13 -> 512 is >20 sigma)
#define BN (BB*NN)

// ---------------- scratch (device globals; no allocation allowed) ----------------
__device__ float g_d[BN];                       // rsqrt(rowsum(A)+1)
__device__ int   g_cnt[BN];                     // neighbor count per row
__device__ short g_idx[(size_t)BN * MAXN];      // ELL neighbor indices (sorted, deterministic)
__device__ float g_f[BN], g_g[BN];              // attention features (reused per layer)
__device__ float g_cmax[BB];                    // per-batch max of g (softmax stabilizer)
__device__ float g_t1[(size_t)BN * FF];         // layer-1 SpMM output
__device__ float g_h [(size_t)BN * HH];         // layer-1 activations (post-relu)
__device__ float g_t2[(size_t)BN * HH];         // layer-2 SpMM output

__device__ __forceinline__ float lrelu(float x) { return x > 0.f ? x : 0.2f * x; }

// ---------------- pass 1: rowsums + ELL compaction (single read of A) ----------------
__global__ void k_build(const float* __restrict__ A) {
    int row = blockIdx.x;                       // 0..BN-1
    const float* Ar = A + (size_t)row * NN;
    int t = threadIdx.x, lane = t & 31, wid = t >> 5;
    __shared__ int   s_w[8], s_wb[8];
    __shared__ int   s_off;
    __shared__ float s_s[8];
    if (t == 0) s_off = 0;
    __syncthreads();
    float sum = 0.f;
    short* idx = g_idx + (size_t)row * MAXN;
    #pragma unroll 1
    for (int ch = 0; ch < NN / 256; ch++) {
        int j = ch * 256 + t;
        float v = Ar[j];
        bool  p = v > 0.f;
        sum += v;
        unsigned m = __ballot_sync(0xffffffffu, p);
        if (lane == 0) s_w[wid] = __popc(m);
        __syncthreads();
        if (t == 0) {
            int base = s_off;
            #pragma unroll
            for (int w = 0; w < 8; w++) { s_wb[w] = base; base += s_w[w]; }
            s_off = base;
        }
        __syncthreads();
        if (p) {
            int pos = s_wb[wid] + __popc(m & ((1u << lane) - 1u));
            idx[pos] = (short)j;                // sorted by j -> deterministic order
        }
        __syncthreads();
    }
    // fixed-order tree reduction of rowsum
    #pragma unroll
    for (int o = 16; o > 0; o >>= 1) sum += __shfl_down_sync(0xffffffffu, sum, o);
    if (lane == 0) s_s[wid] = sum;
    __syncthreads();
    if (t == 0) {
        float tot = 0.f;
        #pragma unroll
        for (int w = 0; w < 8; w++) tot += s_s[w];
        g_d[row]   = rsqrtf(tot + 1.0f);
        g_cnt[row] = s_off;
    }
}

// ---------------- attention feature GEMV: f = Hrow . a_src, g = Hrow . a_dst ----------------
template <int LAYER>
__global__ void k_fg(const float* __restrict__ Xin,
                     const float* __restrict__ asrc, const float* __restrict__ adst) {
    constexpr int D = (LAYER == 1) ? FF : HH;
    int row  = blockIdx.x * (blockDim.x / 32) + (threadIdx.x >> 5);
    int lane = threadIdx.x & 31;
    const float* base = (LAYER == 1) ? Xin : g_h;
    const float* xr = base + (size_t)row * D;
    float fs = 0.f, fd = 0.f;
    #pragma unroll
    for (int k = lane; k < D; k += 32) {
        float x = xr[k];
        fs += x * asrc[k];
        fd += x * adst[k];
    }
    #pragma unroll
    for (int o = 16; o > 0; o >>= 1) {
        fs += __shfl_down_sync(0xffffffffu, fs, o);
        fd += __shfl_down_sync(0xffffffffu, fd, o);
    }
    if (lane == 0) { g_f[row] = fs; g_g[row] = fd; }
}

// ---------------- per-batch max of g (softmax upper bound) ----------------
__global__ void k_gmax() {
    int b = blockIdx.x, t = threadIdx.x;
    float m = -1e30f;
    for (int j = t; j < NN; j += 256) m = fmaxf(m, g_g[b * NN + j]);
    __shared__ float s[256];
    s[t] = m; __syncthreads();
    #pragma unroll
    for (int o = 128; o > 0; o >>= 1) { if (t < o) s[t] = fmaxf(s[t], s[t + o]); __syncthreads(); }
    if (t == 0) g_cmax[b] = s[0];
}

// ---------------- fused masked-softmax + weighted SpMM (one pass over edges) ----------------
// out_i = (d_i / den_i) * sum_{j in nbr(i)} exp(e_ij - c_i) * d_j * (1 + [j==i]) * X_j
template <int LAYER>
__global__ void k_spmm(const float* __restrict__ Xin) {
    constexpr int D = (LAYER == 1) ? FF : HH;
    int row = blockIdx.x;
    int b   = row / NN;
    int il  = row - b * NN;
    int t   = threadIdx.x;
    __shared__ float s_w[D];
    __shared__ int   s_jo[D];
    __shared__ float s_r[D / 32];
    __shared__ float s_den;
    int cnt = g_cnt[row];
    const short* idx = g_idx + (size_t)row * MAXN;
    float fi = g_f[row];
    float c  = lrelu(fi + g_cmax[b]);
    float denp = 0.f, acc = 0.f;
    const float* src = (LAYER == 1) ? Xin : g_h;
    const float* Xb  = src + (size_t)b * NN * D + t;   // column t of this batch
    for (int base = 0; base < cnt; base += D) {
        int e = base + t;
        float ws = 0.f; int j = 0;
        if (e < cnt) {
            j = idx[e];
            float ev = lrelu(fi + g_g[b * NN + j]);
            float w  = __expf(ev - c);
            denp += w;
            ws = w * g_d[b * NN + j];
            if (j == il) ws *= 2.f;                    // self-loop: A_ii+1 = 2
        }
        s_w[t]  = ws;
        s_jo[t] = j * D;                               // precomputed element offset
        __syncthreads();
        int m = min(D, cnt - base);
        #pragma unroll 8
        for (int e2 = 0; e2 < m; e2++)
            acc += s_w[e2] * Xb[s_jo[e2]];
        __syncthreads();
    }
    // fixed-order denominator reduction
    int lane = t & 31, wid = t >> 5;
    #pragma unroll
    for (int o = 16; o > 0; o >>= 1) denp += __shfl_down_sync(0xffffffffu, denp, o);
    if (lane == 0) s_r[wid] = denp;
    __syncthreads();
    if (t == 0) {
        float tot = 0.f;
        #pragma unroll
        for (int w = 0; w < D / 32; w++) tot += s_r[w];
        s_den = tot;
    }
    __syncthreads();
    float di = g_d[row];
    float o;
    if (s_den > 0.f) o = (di / s_den) * acc;
    else             o = (1.0f / NN) * Xb[(size_t)il * D];   // isolated node: uniform softmax, d_i=1
    float* Out = (LAYER == 1) ? g_t1 : g_t2;
    Out[(size_t)row * D + t] = o;
}

// ---------------- dense GEMM: h = relu(t1 @ W1 + b1) ----------------
__global__ void k_gemm1(const float* __restrict__ W1, const float* __restrict__ b1) {
    __shared__ float s_a[16 * FF];
    int t  = threadIdx.x;                       // column 0..255
    int r0 = blockIdx.x * 16;
    for (int i = t; i < 16 * FF; i += 256)
        s_a[i] = g_t1[(size_t)(r0 + i / FF) * FF + (i % FF)];
    __syncthreads();
    float acc[16];
    #pragma unroll
    for (int r = 0; r < 16; r++) acc[r] = 0.f;
    for (int k = 0; k < FF; k++) {
        float wv = W1[k * HH + t];
        #pragma unroll
        for (int r = 0; r < 16; r++) acc[r] += s_a[r * FF + k] * wv;
    }
    float bias = b1[t];
    #pragma unroll
    for (int r = 0; r < 16; r++)
        g_h[(size_t)(r0 + r) * HH + t] = fmaxf(acc[r] + bias, 0.f);
}

// ---------------- dense GEMM: node = t2 @ W2 + b2 ----------------
__global__ void k_gemm2(const float* __restrict__ W2, const float* __restrict__ b2,
                        float* __restrict__ node) {
    __shared__ float s_a[32 * HH];              // 32KB
    int t  = threadIdx.x;                       // 256
    int r0 = blockIdx.x * 32;
    for (int i = t; i < 32 * HH; i += 256)
        s_a[i] = g_t2[(size_t)(r0 + i / HH) * HH + (i % HH)];
    __syncthreads();
    int c = t & 63, rg = t >> 6;                // 64 cols x 4 row groups
    float acc[8];
    #pragma unroll
    for (int r = 0; r < 8; r++) acc[r] = 0.f;
    for (int k = 0; k < HH; k++) {
        float wv = W2[k * CC + c];
        #pragma unroll
        for (int r = 0; r < 8; r++) acc[r] += s_a[(rg + r * 4) * HH + k] * wv;
    }
    float bias = b2[c];
    #pragma unroll
    for (int r = 0; r < 8; r++)
        node[(size_t)(r0 + rg + r * 4) * CC + c] = acc[r] + bias;
}

// ---------------- graph scores: sum over nodes ----------------
__global__ void k_graph(const float* __restrict__ node, float* __restrict__ graph) {
    int b = blockIdx.x, t = threadIdx.x;
    int c = t & 63, part = t >> 6;
    float s = 0.f;
    for (int n = part; n < NN; n += 4)
        s += node[((size_t)b * NN + n) * CC + c];
    __shared__ float sm[256];
    sm[t] = s; __syncthreads();
    if (part == 0)
        graph[b * CC + c] = sm[c] + sm[64 + c] + sm[128 + c] + sm[192 + c];
}

// ---------------- launch ----------------
extern "C" void kernel_launch(void* const* d_in, const int* in_sizes, int n_in,
                              void* d_out, int out_size) {
    const float* X   = (const float*)d_in[0];
    const float* A   = (const float*)d_in[1];
    const float* a1s = (const float*)d_in[2];
    const float* a1d = (const float*)d_in[3];
    const float* W1  = (const float*)d_in[4];
    const float* b1  = (const float*)d_in[5];
    const float* a2s = (const float*)d_in[6];
    const float* a2d = (const float*)d_in[7];
    const float* W2  = (const float*)d_in[8];
    const float* b2  = (const float*)d_in[9];
    float* out   = (float*)d_out;
    float* node  = out;
    float* graph = out + (size_t)BB * NN * CC;

    k_build<<<BN, 256>>>(A);                    // A read exactly once
    k_fg<1><<<BN / 8, 256>>>(X, a1s, a1d);
    k_gmax<<<BB, 256>>>();
    k_spmm<1><<<BN, FF>>>(X);                   // -> g_t1
    k_gemm1<<<BN / 16, 256>>>(W1, b1);          // -> g_h (relu)
    k_fg<2><<<BN / 8, 256>>>(X, a2s, a2d);
    k_gmax<<<BB, 256>>>();
    k_spmm<2><<<BN, HH>>>(X);                   // -> g_t2
    k_gemm2<<<BN / 32, 256>>>(W2, b2, node);    // -> node_scores
    if (out_size >= BB * NN * CC + BB * CC)
        k_graph<<<BB, 256>>>(node, graph);      // -> graph_scores
}

// round 5
// speedup vs baseline: 1.1202x; 1.1202x over previous
#include <cuda_runtime.h>

// Problem constants
#define BB 4
#define NN 2048
#define FF 128
#define HH 256
#define CC 64
#define MAXN 512            // max neighbors per row (mean ~200, sigma ~13)
#define BN (BB*NN)

// ---------------- scratch (device globals; no allocation allowed) ----------------
__device__ float  g_d[BN];                      // rsqrt(rowsum(A)+1)
__device__ int    g_cnt[BN];                    // neighbor count per row
__device__ short  g_idx[(size_t)BN * MAXN];     // ELL neighbor indices (sorted, deterministic)
__device__ float  g_f[BN];                      // attention src feature
__device__ float2 g_gd[BN];                     // {g_j (dst feature), d_j} packed
__device__ float  g_cmax[BB];                   // per-batch max of g (softmax stabilizer)
__device__ float  g_t1[(size_t)BN * FF];        // layer-1 SpMM output
__device__ float  g_h [(size_t)BN * HH];        // layer-1 activations (post-relu)
__device__ float  g_t2[(size_t)BN * HH];        // layer-2 SpMM output

__device__ __forceinline__ float lrelu(float x) { return fmaxf(x, 0.2f * x); }

// ---------------- pass 1: rowsums + ELL compaction (single float4 read of A) ----------------
__global__ void k_build(const float* __restrict__ A) {
    int row = blockIdx.x;                       // 0..BN-1
    const float4* Ar = (const float4*)(A + (size_t)row * NN);
    int t = threadIdx.x, lane = t & 31, wid = t >> 5;
    __shared__ int   s_wcnt[8];
    __shared__ float s_s[8];
    __shared__ int   s_base;
    if (t == 0) s_base = 0;
    __syncthreads();
    float sum = 0.f;
    short* idx = g_idx + (size_t)row * MAXN;
    #pragma unroll
    for (int ch = 0; ch < NN / (256 * 4); ch++) {        // 2 iterations
        int q = ch * 256 + t;                            // float4 index
        float4 v = Ar[q];
        int pred = (v.x > 0.f) | ((v.y > 0.f) << 1) | ((v.z > 0.f) << 2) | ((v.w > 0.f) << 3);
        sum += v.x + v.y + v.z + v.w;
        int c = __popc(pred);
        int sc = c;                                      // warp inclusive scan
        #pragma unroll
        for (int o = 1; o < 32; o <<= 1) {
            int n = __shfl_up_sync(0xffffffffu, sc, o);
            if (lane >= o) sc += n;
        }
        if (lane == 31) s_wcnt[wid] = sc;
        __syncthreads();
        int wbase = s_base;
        #pragma unroll
        for (int w = 0; w < 8; w++) if (w < wid) wbase += s_wcnt[w];
        int pos = wbase + sc - c;                        // exclusive position
        int j0 = q * 4;
        if (pred & 1) idx[pos++] = (short)(j0);
        if (pred & 2) idx[pos++] = (short)(j0 + 1);
        if (pred & 4) idx[pos++] = (short)(j0 + 2);
        if (pred & 8) idx[pos++] = (short)(j0 + 3);
        __syncthreads();
        if (t == 0) {
            int tot = 0;
            #pragma unroll
            for (int w = 0; w < 8; w++) tot += s_wcnt[w];
            s_base += tot;
        }
        __syncthreads();
    }
    // fixed-order rowsum reduction
    #pragma unroll
    for (int o = 16; o > 0; o >>= 1) sum += __shfl_down_sync(0xffffffffu, sum, o);
    if (lane == 0) s_s[wid] = sum;
    __syncthreads();
    if (t == 0) {
        float tot = 0.f;
        #pragma unroll
        for (int w = 0; w < 8; w++) tot += s_s[w];
        g_d[row]   = rsqrtf(tot + 1.0f);
        g_cnt[row] = s_base;
    }
}

// ---------------- attention features: f = row.a_src, packed {g=row.a_dst, d} ----------------
template <int LAYER>
__global__ void k_fg(const float* __restrict__ Xin,
                     const float* __restrict__ asrc, const float* __restrict__ adst) {
    constexpr int D = (LAYER == 1) ? FF : HH;
    int row  = blockIdx.x * (blockDim.x / 32) + (threadIdx.x >> 5);
    int lane = threadIdx.x & 31;
    const float* base = (LAYER == 1) ? Xin : g_h;
    const float4* xr = (const float4*)(base + (size_t)row * D);
    const float4* s4 = (const float4*)asrc;
    const float4* d4 = (const float4*)adst;
    float fs = 0.f, fd = 0.f;
    #pragma unroll
    for (int k = lane; k < D / 4; k += 32) {
        float4 x = xr[k], a = s4[k], b = d4[k];
        fs += x.x * a.x + x.y * a.y + x.z * a.z + x.w * a.w;
        fd += x.x * b.x + x.y * b.y + x.z * b.z + x.w * b.w;
    }
    #pragma unroll
    for (int o = 16; o > 0; o >>= 1) {
        fs += __shfl_down_sync(0xffffffffu, fs, o);
        fd += __shfl_down_sync(0xffffffffu, fd, o);
    }
    if (lane == 0) {
        g_f[row]  = fs;
        g_gd[row] = make_float2(fd, g_d[row]);
    }
}

// ---------------- per-batch max of g ----------------
__global__ void k_gmax() {
    int b = blockIdx.x, t = threadIdx.x;
    float m = -1e30f;
    for (int j = t; j < NN; j += 256) m = fmaxf(m, g_gd[b * NN + j].x);
    __shared__ float s[256];
    s[t] = m; __syncthreads();
    #pragma unroll
    for (int o = 128; o > 0; o >>= 1) { if (t < o) s[t] = fmaxf(s[t], s[t + o]); __syncthreads(); }
    if (t == 0) g_cmax[b] = s[0];
}

// ---------------- fused masked-softmax + weighted SpMM ----------------
// Phase 1: 256 threads compute per-edge {ws, j*D} into smem (+ denominator).
// Phase 2: 8 warps split edges; each warp covers the full D columns with float4;
//          edge scalars broadcast via shfl (no per-edge LDS).
template <int LAYER>
__global__ void __launch_bounds__(256) k_spmm(const float* __restrict__ Xin) {
    constexpr int D = (LAYER == 1) ? FF : HH;
    constexpr int V2 = (D == 256) ? 1 : 0;
    int row = blockIdx.x;
    int b   = row >> 11;
    int il  = row & (NN - 1);
    int t   = threadIdx.x, lane = t & 31, w = t >> 5;
    __shared__ float2 s_ed[MAXN];               // {ws, bitcast(j*D)}
    __shared__ float  s_den[8];
    __shared__ float  s_red[8 * D];
    int cnt = g_cnt[row];
    const short* idx = g_idx + (size_t)row * MAXN;
    float fi = g_f[row];
    float c  = lrelu(fi + g_cmax[b]);
    // ---- phase 1: edge scalars ----
    float denp = 0.f;
    for (int e = t; e < cnt; e += 256) {
        int j = idx[e];
        float2 gd = g_gd[b * NN + j];
        float ev = lrelu(fi + gd.x);
        float wv = __expf(ev - c);
        denp += wv;
        float ws = wv * gd.y;
        if (j == il) ws *= 2.f;                 // self-loop: A_ii+1 = 2
        s_ed[e] = make_float2(ws, __int_as_float(j * D));
    }
    #pragma unroll
    for (int o = 16; o > 0; o >>= 1) denp += __shfl_down_sync(0xffffffffu, denp, o);
    if (lane == 0) s_den[w] = denp;
    __syncthreads();
    // ---- phase 2: gather-accumulate ----
    const float* src = (LAYER == 1) ? Xin : g_h;
    const float4* Xb = (const float4*)(src + (size_t)b * NN * D);
    float4 acc0 = make_float4(0.f, 0.f, 0.f, 0.f);
    float4 acc1 = make_float4(0.f, 0.f, 0.f, 0.f);
    for (int e0 = w * 32; e0 < cnt; e0 += 256) {
        int e = e0 + lane;
        float2 my = (e < cnt) ? s_ed[e] : make_float2(0.f, 0.f);
        int nk = min(32, cnt - e0);
        for (int k = 0; k < nk; k++) {
            float wk = __shfl_sync(0xffffffffu, my.x, k);
            int   ok = __float_as_int(__shfl_sync(0xffffffffu, my.y, k));
            const float4* xp = Xb + (ok >> 2) + lane;
            float4 x0 = xp[0];
            acc0.x += wk * x0.x; acc0.y += wk * x0.y;
            acc0.z += wk * x0.z; acc0.w += wk * x0.w;
            if (V2) {
                float4 x1 = xp[32];
                acc1.x += wk * x1.x; acc1.y += wk * x1.y;
                acc1.z += wk * x1.z; acc1.w += wk * x1.w;
            }
        }
    }
    float* red = s_red + w * D;
    *(float4*)(red + lane * 4) = acc0;
    if (V2) *(float4*)(red + 128 + lane * 4) = acc1;
    __syncthreads();
    // ---- final cross-warp reduce + scale + write ----
    if (t < D) {
        float den = 0.f;
        #pragma unroll
        for (int ww = 0; ww < 8; ww++) den += s_den[ww];
        float a = 0.f;
        #pragma unroll
        for (int ww = 0; ww < 8; ww++) a += s_red[ww * D + t];
        float di = g_d[row];
        float o;
        if (den > 0.f) o = (di / den) * a;
        else           o = (1.0f / NN) * src[((size_t)b * NN + il) * D + t];  // isolated node
        float* Out = (LAYER == 1) ? g_t1 : g_t2;
        Out[(size_t)row * D + t] = o;
    }
}

// ---------------- dense GEMM: h = relu(t1 @ W1 + b1) ----------------
__global__ void k_gemm1(const float* __restrict__ W1, const float* __restrict__ b1) {
    __shared__ float s_a[16 * FF];
    int t  = threadIdx.x;                       // column 0..255
    int r0 = blockIdx.x * 16;
    for (int i = t; i < 16 * FF; i += 256)
        s_a[i] = g_t1[(size_t)(r0 + i / FF) * FF + (i % FF)];
    __syncthreads();
    float acc[16];
    #pragma unroll
    for (int r = 0; r < 16; r++) acc[r] = 0.f;
    for (int k = 0; k < FF; k++) {
        float wv = W1[k * HH + t];
        #pragma unroll
        for (int r = 0; r < 16; r++) acc[r] += s_a[r * FF + k] * wv;
    }
    float bias = b1[t];
    #pragma unroll
    for (int r = 0; r < 16; r++)
        g_h[(size_t)(r0 + r) * HH + t] = fmaxf(acc[r] + bias, 0.f);
}

// ---------------- dense GEMM: node = t2 @ W2 + b2 ----------------
__global__ void k_gemm2(const float* __restrict__ W2, const float* __restrict__ b2,
                        float* __restrict__ node) {
    __shared__ float s_a[32 * HH];              // 32KB
    int t  = threadIdx.x;                       // 256
    int r0 = blockIdx.x * 32;
    for (int i = t; i < 32 * HH; i += 256)
        s_a[i] = g_t2[(size_t)(r0 + i / HH) * HH + (i % HH)];
    __syncthreads();
    int c = t & 63, rg = t >> 6;                // 64 cols x 4 row groups
    float acc[8];
    #pragma unroll
    for (int r = 0; r < 8; r++) acc[r] = 0.f;
    for (int k = 0; k < HH; k++) {
        float wv = W2[k * CC + c];
        #pragma unroll
        for (int r = 0; r < 8; r++) acc[r] += s_a[(rg + r * 4) * HH + k] * wv;
    }
    float bias = b2[c];
    #pragma unroll
    for (int r = 0; r < 8; r++)
        node[(size_t)(r0 + rg + r * 4) * CC + c] = acc[r] + bias;
}

// ---------------- graph scores: sum over nodes ----------------
__global__ void k_graph(const float* __restrict__ node, float* __restrict__ graph) {
    int b = blockIdx.x, t = threadIdx.x;
    int c = t & 63, part = t >> 6;
    float s = 0.f;
    for (int n = part; n < NN; n += 4)
        s += node[((size_t)b * NN + n) * CC + c];
    __shared__ float sm[256];
    sm[t] = s; __syncthreads();
    if (part == 0)
        graph[b * CC + c] = sm[c] + sm[64 + c] + sm[128 + c] + sm[192 + c];
}

// ---------------- launch ----------------
extern "C" void kernel_launch(void* const* d_in, const int* in_sizes, int n_in,
                              void* d_out, int out_size) {
    const float* X   = (const float*)d_in[0];
    const float* A   = (const float*)d_in[1];
    const float* a1s = (const float*)d_in[2];
    const float* a1d = (const float*)d_in[3];
    const float* W1  = (const float*)d_in[4];
    const float* b1  = (const float*)d_in[5];
    const float* a2s = (const float*)d_in[6];
    const float* a2d = (const float*)d_in[7];
    const float* W2  = (const float*)d_in[8];
    const float* b2  = (const float*)d_in[9];
    float* out   = (float*)d_out;
    float* node  = out;
    float* graph = out + (size_t)BB * NN * CC;

    k_build<<<BN, 256>>>(A);                    // A read exactly once
    k_fg<1><<<BN / 8, 256>>>(X, a1s, a1d);
    k_gmax<<<BB, 256>>>();
    k_spmm<1><<<BN, 256>>>(X);                  // -> g_t1
    k_gemm1<<<BN / 16, 256>>>(W1, b1);          // -> g_h (relu)
    k_fg<2><<<BN / 8, 256>>>(X, a2s, a2d);
    k_gmax<<<BB, 256>>>();
    k_spmm<2><<<BN, 256>>>(X);                  // -> g_t2
    k_gemm2<<<BN / 32, 256>>>(W2, b2, node);    // -> node_scores
    if (out_size >= BB * NN * CC + BB * CC)
        k_graph<<<BB, 256>>>(node, graph);      // -> graph_scores
}

// round 6
// speedup vs baseline: 1.2097x; 1.0799x over previous
#include <cuda_runtime.h>

// Problem constants
#define BB 4
#define NN 2048
#define FF 128
#define HH 256
#define CC 64
#define MAXN 512            // max neighbors per row (mean ~200, sigma ~13)
#define BN (BB*NN)

// ---------------- scratch (device globals; no allocation allowed) ----------------
__device__ float  g_d[BN];                      // rsqrt(rowsum(A)+1)
__device__ int    g_cnt[BN];                    // neighbor count per row
__device__ short  g_idx[(size_t)BN * MAXN];     // ELL neighbor indices (sorted, deterministic)
__device__ float  g_f[BN];                      // attention src feature
__device__ float2 g_gd[BN];                     // {g_j (dst feature), d_j} packed
__device__ float  g_cmax[BB];                   // per-batch max of g (softmax stabilizer)
__device__ float  g_t1[(size_t)BN * FF];        // layer-1 SpMM output
__device__ float  g_h [(size_t)BN * HH];        // layer-1 activations (post-relu)
__device__ float  g_t2[(size_t)BN * HH];        // layer-2 SpMM output

__device__ __forceinline__ float lrelu(float x) { return fmaxf(x, 0.2f * x); }

// ---------------- pass 1: rowsums + ELL compaction (single float4 read of A) ----------------
__global__ void k_build(const float* __restrict__ A) {
    int row = blockIdx.x;                       // 0..BN-1
    const float4* Ar = (const float4*)(A + (size_t)row * NN);
    int t = threadIdx.x, lane = t & 31, wid = t >> 5;
    __shared__ int   s_wcnt[8];
    __shared__ float s_s[8];
    __shared__ int   s_base;
    if (t == 0) s_base = 0;
    __syncthreads();
    float sum = 0.f;
    short* idx = g_idx + (size_t)row * MAXN;
    #pragma unroll
    for (int ch = 0; ch < NN / (256 * 4); ch++) {        // 2 iterations
        int q = ch * 256 + t;                            // float4 index
        float4 v = Ar[q];
        int pred = (v.x > 0.f) | ((v.y > 0.f) << 1) | ((v.z > 0.f) << 2) | ((v.w > 0.f) << 3);
        sum += v.x + v.y + v.z + v.w;
        int c = __popc(pred);
        int sc = c;                                      // warp inclusive scan
        #pragma unroll
        for (int o = 1; o < 32; o <<= 1) {
            int n = __shfl_up_sync(0xffffffffu, sc, o);
            if (lane >= o) sc += n;
        }
        if (lane == 31) s_wcnt[wid] = sc;
        __syncthreads();
        int wbase = s_base;
        #pragma unroll
        for (int w = 0; w < 8; w++) if (w < wid) wbase += s_wcnt[w];
        int pos = wbase + sc - c;                        // exclusive position
        int j0 = q * 4;
        if (pred & 1) idx[pos++] = (short)(j0);
        if (pred & 2) idx[pos++] = (short)(j0 + 1);
        if (pred & 4) idx[pos++] = (short)(j0 + 2);
        if (pred & 8) idx[pos++] = (short)(j0 + 3);
        __syncthreads();
        if (t == 0) {
            int tot = 0;
            #pragma unroll
            for (int w = 0; w < 8; w++) tot += s_wcnt[w];
            s_base += tot;
        }
        __syncthreads();
    }
    // fixed-order rowsum reduction
    #pragma unroll
    for (int o = 16; o > 0; o >>= 1) sum += __shfl_down_sync(0xffffffffu, sum, o);
    if (lane == 0) s_s[wid] = sum;
    __syncthreads();
    if (t == 0) {
        float tot = 0.f;
        #pragma unroll
        for (int w = 0; w < 8; w++) tot += s_s[w];
        g_d[row]   = rsqrtf(tot + 1.0f);
        g_cnt[row] = s_base;
    }
}

// ---------------- attention features: f = row.a_src, packed {g=row.a_dst, d} ----------------
template <int LAYER>
__global__ void k_fg(const float* __restrict__ Xin,
                     const float* __restrict__ asrc, const float* __restrict__ adst) {
    constexpr int D = (LAYER == 1) ? FF : HH;
    int row  = blockIdx.x * (blockDim.x / 32) + (threadIdx.x >> 5);
    int lane = threadIdx.x & 31;
    const float* base = (LAYER == 1) ? Xin : g_h;
    const float4* xr = (const float4*)(base + (size_t)row * D);
    const float4* s4 = (const float4*)asrc;
    const float4* d4 = (const float4*)adst;
    float fs = 0.f, fd = 0.f;
    #pragma unroll
    for (int k = lane; k < D / 4; k += 32) {
        float4 x = xr[k], a = s4[k], b = d4[k];
        fs += x.x * a.x + x.y * a.y + x.z * a.z + x.w * a.w;
        fd += x.x * b.x + x.y * b.y + x.z * b.z + x.w * b.w;
    }
    #pragma unroll
    for (int o = 16; o > 0; o >>= 1) {
        fs += __shfl_down_sync(0xffffffffu, fs, o);
        fd += __shfl_down_sync(0xffffffffu, fd, o);
    }
    if (lane == 0) {
        g_f[row]  = fs;
        g_gd[row] = make_float2(fd, g_d[row]);
    }
}

// ---------------- per-batch max of g ----------------
__global__ void k_gmax() {
    int b = blockIdx.x, t = threadIdx.x;
    float m = -1e30f;
    for (int j = t; j < NN; j += 256) m = fmaxf(m, g_gd[b * NN + j].x);
    __shared__ float s[256];
    s[t] = m; __syncthreads();
    #pragma unroll
    for (int o = 128; o > 0; o >>= 1) { if (t < o) s[t] = fmaxf(s[t], s[t + o]); __syncthreads(); }
    if (t == 0) g_cmax[b] = s[0];
}

// ---------------- fused masked-softmax + weighted SpMM ----------------
// Phase 1: 256 threads compute per-edge {ws, float4-offset} into smem (+ denominator),
//          padding the list with zero records to a multiple of the unroll stride.
// Phase 2: 8 warps split edges, fixed-unroll inner loop (no bounds checks):
//          per edge: 1 LDS.64 broadcast + NL LDG.128 + FFMA. High MLP, no SHFL.
template <int LAYER>
__global__ void __launch_bounds__(256) k_spmm(const float* __restrict__ Xin) {
    constexpr int D  = (LAYER == 1) ? FF : HH;
    constexpr int UN = (LAYER == 1) ? 4 : 2;     // edges per warp per iteration
    constexpr int STRIDE = 8 * UN;               // edges per block per iteration
    int row = blockIdx.x;
    int b   = row >> 11;
    int il  = row & (NN - 1);
    int t   = threadIdx.x, lane = t & 31, w = t >> 5;
    __shared__ float2 s_ed[MAXN];               // {ws, bitcast(float4 offset)}
    __shared__ float  s_den[8];
    __shared__ float  s_red[8 * D];
    int cnt  = g_cnt[row];
    int cntp = (cnt + STRIDE - 1) & ~(STRIDE - 1);
    const short* idx = g_idx + (size_t)row * MAXN;
    float fi = g_f[row];
    float c  = lrelu(fi + g_cmax[b]);
    // ---- phase 1: edge scalars (+ zero padding to cntp) ----
    float denp = 0.f;
    for (int e = t; e < cntp; e += 256) {
        float2 rec = make_float2(0.f, __int_as_float(0));
        if (e < cnt) {
            int j = idx[e];
            float2 gd = g_gd[b * NN + j];
            float ev = lrelu(fi + gd.x);
            float wv = __expf(ev - c);
            denp += wv;
            float ws = wv * gd.y;
            if (j == il) ws *= 2.f;              // self-loop: A_ii+1 = 2
            rec = make_float2(ws, __int_as_float(j * (D / 4)));
        }
        s_ed[e] = rec;
    }
    #pragma unroll
    for (int o = 16; o > 0; o >>= 1) denp += __shfl_down_sync(0xffffffffu, denp, o);
    if (lane == 0) s_den[w] = denp;
    __syncthreads();
    // ---- phase 2: gather-accumulate, fixed unroll ----
    const float* src = (LAYER == 1) ? Xin : g_h;
    const float4* Xb = (const float4*)(src + (size_t)b * NN * D) + lane;
    float4 aA = make_float4(0.f, 0.f, 0.f, 0.f);
    float4 aB = make_float4(0.f, 0.f, 0.f, 0.f);
    float4 aA1 = make_float4(0.f, 0.f, 0.f, 0.f);
    float4 aB1 = make_float4(0.f, 0.f, 0.f, 0.f);
    if (UN == 4) {
        for (int e0 = w * 4; e0 < cntp; e0 += STRIDE) {
            float2 r0 = s_ed[e0],     r1 = s_ed[e0 + 1];
            float2 r2 = s_ed[e0 + 2], r3 = s_ed[e0 + 3];
            float4 x0 = Xb[__float_as_int(r0.y)];
            float4 x1 = Xb[__float_as_int(r1.y)];
            float4 x2 = Xb[__float_as_int(r2.y)];
            float4 x3 = Xb[__float_as_int(r3.y)];
            aA.x += r0.x * x0.x; aA.y += r0.x * x0.y; aA.z += r0.x * x0.z; aA.w += r0.x * x0.w;
            aB.x += r1.x * x1.x; aB.y += r1.x * x1.y; aB.z += r1.x * x1.z; aB.w += r1.x * x1.w;
            aA.x += r2.x * x2.x; aA.y += r2.x * x2.y; aA.z += r2.x * x2.z; aA.w += r2.x * x2.w;
            aB.x += r3.x * x3.x; aB.y += r3.x * x3.y; aB.z += r3.x * x3.z; aB.w += r3.x * x3.w;
        }
    } else {
        for (int e0 = w * 2; e0 < cntp; e0 += STRIDE) {
            float2 r0 = s_ed[e0], r1 = s_ed[e0 + 1];
            int o0 = __float_as_int(r0.y), o1 = __float_as_int(r1.y);
            float4 x0  = Xb[o0];
            float4 x0b = Xb[o0 + 32];
            float4 x1  = Xb[o1];
            float4 x1b = Xb[o1 + 32];
            aA.x  += r0.x * x0.x;  aA.y  += r0.x * x0.y;  aA.z  += r0.x * x0.z;  aA.w  += r0.x * x0.w;
            aA1.x += r0.x * x0b.x; aA1.y += r0.x * x0b.y; aA1.z += r0.x * x0b.z; aA1.w += r0.x * x0b.w;
            aB.x  += r1.x * x1.x;  aB.y  += r1.x * x1.y;  aB.z  += r1.x * x1.z;  aB.w  += r1.x * x1.w;
            aB1.x += r1.x * x1b.x; aB1.y += r1.x * x1b.y; aB1.z += r1.x * x1b.z; aB1.w += r1.x * x1b.w;
        }
    }
    float* red = s_red + w * D;
    {
        float4 s0 = make_float4(aA.x + aB.x, aA.y + aB.y, aA.z + aB.z, aA.w + aB.w);
        *(float4*)(red + lane * 4) = s0;
        if (D == 256) {
            float4 s1 = make_float4(aA1.x + aB1.x, aA1.y + aB1.y, aA1.z + aB1.z, aA1.w + aB1.w);
            *(float4*)(red + 128 + lane * 4) = s1;
        }
    }
    __syncthreads();
    // ---- final cross-warp reduce + scale + write ----
    if (t < D) {
        float den = 0.f;
        #pragma unroll
        for (int ww = 0; ww < 8; ww++) den += s_den[ww];
        float a = 0.f;
        #pragma unroll
        for (int ww = 0; ww < 8; ww++) a += s_red[ww * D + t];
        float di = g_d[row];
        float o;
        if (den > 0.f) o = (di / den) * a;
        else           o = (1.0f / NN) * src[((size_t)b * NN + il) * D + t];  // isolated node
        float* Out = (LAYER == 1) ? g_t1 : g_t2;
        Out[(size_t)row * D + t] = o;
    }
}

// ---------------- dense GEMM: h = relu(t1 @ W1 + b1) ----------------
__global__ void k_gemm1(const float* __restrict__ W1, const float* __restrict__ b1) {
    __shared__ float s_a[16 * FF];
    int t  = threadIdx.x;                       // column 0..255
    int r0 = blockIdx.x * 16;
    for (int i = t; i < 16 * FF; i += 256)
        s_a[i] = g_t1[(size_t)(r0 + i / FF) * FF + (i % FF)];
    __syncthreads();
    float acc[16];
    #pragma unroll
    for (int r = 0; r < 16; r++) acc[r] = 0.f;
    for (int k = 0; k < FF; k++) {
        float wv = W1[k * HH + t];
        #pragma unroll
        for (int r = 0; r < 16; r++) acc[r] += s_a[r * FF + k] * wv;
    }
    float bias = b1[t];
    #pragma unroll
    for (int r = 0; r < 16; r++)
        g_h[(size_t)(r0 + r) * HH + t] = fmaxf(acc[r] + bias, 0.f);
}

// ---------------- dense GEMM: node = t2 @ W2 + b2 ----------------
__global__ void k_gemm2(const float* __restrict__ W2, const float* __restrict__ b2,
                        float* __restrict__ node) {
    __shared__ float s_a[32 * HH];              // 32KB
    int t  = threadIdx.x;                       // 256
    int r0 = blockIdx.x * 32;
    for (int i = t; i < 32 * HH; i += 256)
        s_a[i] = g_t2[(size_t)(r0 + i / HH) * HH + (i % HH)];
    __syncthreads();
    int c = t & 63, rg = t >> 6;                // 64 cols x 4 row groups
    float acc[8];
    #pragma unroll
    for (int r = 0; r < 8; r++) acc[r] = 0.f;
    for (int k = 0; k < HH; k++) {
        float wv = W2[k * CC + c];
        #pragma unroll
        for (int r = 0; r < 8; r++) acc[r] += s_a[(rg + r * 4) * HH + k] * wv;
    }
    float bias = b2[c];
    #pragma unroll
    for (int r = 0; r < 8; r++)
        node[(size_t)(r0 + rg + r * 4) * CC + c] = acc[r] + bias;
}

// ---------------- graph scores: sum over nodes ----------------
__global__ void k_graph(const float* __restrict__ node, float* __restrict__ graph) {
    int b = blockIdx.x, t = threadIdx.x;
    int c = t & 63, part = t >> 6;
    float s = 0.f;
    for (int n = part; n < NN; n += 4)
        s += node[((size_t)b * NN + n) * CC + c];
    __shared__ float sm[256];
    sm[t] = s; __syncthreads();
    if (part == 0)
        graph[b * CC + c] = sm[c] + sm[64 + c] + sm[128 + c] + sm[192 + c];
}

// ---------------- launch ----------------
extern "C" void kernel_launch(void* const* d_in, const int* in_sizes, int n_in,
                              void* d_out, int out_size) {
    const float* X   = (const float*)d_in[0];
    const float* A   = (const float*)d_in[1];
    const float* a1s = (const float*)d_in[2];
    const float* a1d = (const float*)d_in[3];
    const float* W1  = (const float*)d_in[4];
    const float* b1  = (const float*)d_in[5];
    const float* a2s = (const float*)d_in[6];
    const float* a2d = (const float*)d_in[7];
    const float* W2  = (const float*)d_in[8];
    const float* b2  = (const float*)d_in[9];
    float* out   = (float*)d_out;
    float* node  = out;
    float* graph = out + (size_t)BB * NN * CC;

    k_build<<<BN, 256>>>(A);                    // A read exactly once
    k_fg<1><<<BN / 8, 256>>>(X, a1s, a1d);
    k_gmax<<<BB, 256>>>();
    k_spmm<1><<<BN, 256>>>(X);                  // -> g_t1
    k_gemm1<<<BN / 16, 256>>>(W1, b1);          // -> g_h (relu)
    k_fg<2><<<BN / 8, 256>>>(X, a2s, a2d);
    k_gmax<<<BB, 256>>>();
    k_spmm<2><<<BN, 256>>>(X);                  // -> g_t2
    k_gemm2<<<BN / 32, 256>>>(W2, b2, node);    // -> node_scores
    if (out_size >= BB * NN * CC + BB * CC)
        k_graph<<<BB, 256>>>(node, graph);      // -> graph_scores
}